// round 1
// baseline (speedup 1.0000x reference)
#include <cuda_runtime.h>
#include <math.h>

// ---------------------------------------------------------------------------
// FullAttention baseline (fp32 exact)
//   x[4096,1024] @ Wqkv[1024,3072] + b -> qkv
//   16-head flash attention (T=4096, Dh=64)
//   attn[4096,1024] @ Wout[1024,1024] + b -> out
// ---------------------------------------------------------------------------

#define T_SEQ   4096
#define C_DIM   1024
#define H_NUM   16
#define DH      64
#define QKV_N   3072

// Scratch (device globals: allocation-free per harness rules)
__device__ float g_qkv[(size_t)T_SEQ * QKV_N];   // 48 MB
__device__ float g_attn[(size_t)T_SEQ * C_DIM];  // 16 MB

// ---------------------------------------------------------------------------
// GEMM: C[M,N] = A[M,K] @ B[K,N] + bias[N]   (row-major, all dims % 64 == 0,
// K % 16 == 0). 64x64 tile, BK=16, 256 threads, 4x4 micro-tile per thread.
// ---------------------------------------------------------------------------
#define BM 64
#define BN 64
#define BK 16

__global__ __launch_bounds__(256) void gemm_bias_kernel(
    const float* __restrict__ A, const float* __restrict__ B,
    const float* __restrict__ bias, float* __restrict__ C,
    int M, int N, int K)
{
    __shared__ float As[BK][BM];
    __shared__ float Bs[BK][BN];

    const int tid = threadIdx.x;
    const int tx = tid & 15;          // 0..15  (N direction)
    const int ty = tid >> 4;          // 0..15  (M direction)
    const int blockRow = blockIdx.y * BM;
    const int blockCol = blockIdx.x * BN;

    float acc[4][4] = {};

    // A-load mapping: each thread loads one float4 of a row's K-slice
    const int a_row  = tid >> 2;        // 0..63
    const int a_kgrp = (tid & 3) * 4;   // 0,4,8,12
    // B-load mapping: each thread loads one float4 of a K-row's N-slice
    const int b_krow = tid >> 4;        // 0..15
    const int b_col  = (tid & 15) * 4;  // 0..60

    for (int k0 = 0; k0 < K; k0 += BK) {
        float4 av = *(const float4*)(A + (size_t)(blockRow + a_row) * K + k0 + a_kgrp);
        As[a_kgrp + 0][a_row] = av.x;
        As[a_kgrp + 1][a_row] = av.y;
        As[a_kgrp + 2][a_row] = av.z;
        As[a_kgrp + 3][a_row] = av.w;

        *(float4*)&Bs[b_krow][b_col] =
            *(const float4*)(B + (size_t)(k0 + b_krow) * N + blockCol + b_col);

        __syncthreads();

        #pragma unroll
        for (int kk = 0; kk < BK; kk++) {
            float4 a4 = *(const float4*)&As[kk][ty * 4];
            float4 b4 = *(const float4*)&Bs[kk][tx * 4];
            float a[4] = {a4.x, a4.y, a4.z, a4.w};
            float b[4] = {b4.x, b4.y, b4.z, b4.w};
            #pragma unroll
            for (int i = 0; i < 4; i++)
                #pragma unroll
                for (int j = 0; j < 4; j++)
                    acc[i][j] += a[i] * b[j];
        }
        __syncthreads();
    }

    const int col = blockCol + tx * 4;
    float4 bv = *(const float4*)(bias + col);
    #pragma unroll
    for (int i = 0; i < 4; i++) {
        const int row = blockRow + ty * 4 + i;
        float4 o;
        o.x = acc[i][0] + bv.x;
        o.y = acc[i][1] + bv.y;
        o.z = acc[i][2] + bv.z;
        o.w = acc[i][3] + bv.w;
        *(float4*)(C + (size_t)row * N + col) = o;
    }
}

// ---------------------------------------------------------------------------
// Flash attention, fp32. One thread owns one query row (64 threads/block,
// 64 query rows/block). KV tiles of 64 rows staged in SMEM.
// grid = (T/64, H)
// ---------------------------------------------------------------------------
__global__ __launch_bounds__(64) void attn_kernel(
    const float* __restrict__ qkv, float* __restrict__ attn_out)
{
    __shared__ float Ks[64][64];
    __shared__ float Vs[64][64];

    const int h   = blockIdx.y;
    const int qb  = blockIdx.x;
    const int tid = threadIdx.x;
    const int row = qb * 64 + tid;

    // load this thread's q row into registers
    float q[DH];
    const float* qptr = qkv + (size_t)row * QKV_N + h * DH;
    #pragma unroll
    for (int d = 0; d < DH; d += 4) {
        float4 t = *(const float4*)(qptr + d);
        q[d] = t.x; q[d+1] = t.y; q[d+2] = t.z; q[d+3] = t.w;
    }

    float o[DH];
    #pragma unroll
    for (int d = 0; d < DH; d++) o[d] = 0.0f;
    float m = -INFINITY;
    float l = 0.0f;
    const float scale = 0.125f;   // 1/sqrt(64)

    #pragma unroll 1
    for (int kb = 0; kb < T_SEQ / 64; kb++) {
        __syncthreads();   // protect previous tile reads
        const float* kbase = qkv + (size_t)(kb * 64) * QKV_N + C_DIM + h * DH;
        const float* vbase = kbase + C_DIM;
        // 64 threads load 64x64 K and V tiles (float4 granularity)
        #pragma unroll 1
        for (int i = tid; i < 64 * 16; i += 64) {
            const int r  = i >> 4;
            const int c4 = (i & 15) * 4;
            *(float4*)&Ks[r][c4] = *(const float4*)(kbase + (size_t)r * QKV_N + c4);
            *(float4*)&Vs[r][c4] = *(const float4*)(vbase + (size_t)r * QKV_N + c4);
        }
        __syncthreads();

        #pragma unroll 1
        for (int j = 0; j < 64; j++) {
            float s0 = 0.f, s1 = 0.f, s2 = 0.f, s3 = 0.f;
            #pragma unroll
            for (int d = 0; d < DH; d += 4) {
                float4 kv = *(const float4*)&Ks[j][d];
                s0 += q[d]     * kv.x;
                s1 += q[d + 1] * kv.y;
                s2 += q[d + 2] * kv.z;
                s3 += q[d + 3] * kv.w;
            }
            float s = ((s0 + s1) + (s2 + s3)) * scale;

            if (s > m) {
                float alpha = __expf(m - s);   // exp(-inf)=0 handles first iter
                l *= alpha;
                #pragma unroll
                for (int d = 0; d < DH; d++) o[d] *= alpha;
                m = s;
            }
            float p = __expf(s - m);
            l += p;
            #pragma unroll
            for (int d = 0; d < DH; d += 4) {
                float4 vv = *(const float4*)&Vs[j][d];
                o[d]     += p * vv.x;
                o[d + 1] += p * vv.y;
                o[d + 2] += p * vv.z;
                o[d + 3] += p * vv.w;
            }
        }
    }

    const float inv_l = 1.0f / l;
    float* optr = attn_out + (size_t)row * C_DIM + h * DH;
    #pragma unroll
    for (int d = 0; d < DH; d += 4) {
        float4 t;
        t.x = o[d]     * inv_l;
        t.y = o[d + 1] * inv_l;
        t.z = o[d + 2] * inv_l;
        t.w = o[d + 3] * inv_l;
        *(float4*)(optr + d) = t;
    }
}

// ---------------------------------------------------------------------------
extern "C" void kernel_launch(void* const* d_in, const int* in_sizes, int n_in,
                              void* d_out, int out_size)
{
    const float* x     = (const float*)d_in[0];
    const float* Wqkv  = (const float*)d_in[1];
    const float* bqkv  = (const float*)d_in[2];
    const float* Wout  = (const float*)d_in[3];
    const float* bout  = (const float*)d_in[4];
    float* out = (float*)d_out;

    float* qkv;
    float* attn;
    cudaGetSymbolAddress((void**)&qkv,  g_qkv);
    cudaGetSymbolAddress((void**)&attn, g_attn);

    // 1) QKV projection: [4096,1024] @ [1024,3072] + b
    gemm_bias_kernel<<<dim3(QKV_N / BN, T_SEQ / BM), 256>>>(
        x, Wqkv, bqkv, qkv, T_SEQ, QKV_N, C_DIM);

    // 2) Multi-head flash attention
    attn_kernel<<<dim3(T_SEQ / 64, H_NUM), 64>>>(qkv, attn);

    // 3) Output projection: [4096,1024] @ [1024,1024] + b
    gemm_bias_kernel<<<dim3(C_DIM / BN, T_SEQ / BM), 256>>>(
        attn, Wout, bout, out, T_SEQ, C_DIM, C_DIM);
}

// round 2
// speedup vs baseline: 4.1151x; 4.1151x over previous
#include <cuda_runtime.h>
#include <math.h>

// ---------------------------------------------------------------------------
// FullAttention, tf32 tensor-core pipeline (mma.sync m16n8k8)
//   x[4096,1024] @ Wqkv[1024,3072] + b -> qkv
//   16-head flash attention (T=4096, Dh=64), tf32 QK^T and PV
//   attn[4096,1024] @ Wout[1024,1024] + b -> out
// ---------------------------------------------------------------------------

#define T_SEQ   4096
#define C_DIM   1024
#define H_NUM   16
#define QKV_N   3072

__device__ float g_qkv[(size_t)T_SEQ * QKV_N];   // 48 MB scratch
__device__ float g_attn[(size_t)T_SEQ * C_DIM];  // 16 MB scratch

__device__ __forceinline__ unsigned f2tf32(float x) {
    unsigned r;
    asm("cvt.rna.tf32.f32 %0, %1;" : "=r"(r) : "f"(x));
    return r;
}

__device__ __forceinline__ void mma_tf32(float* c, const unsigned* a, const unsigned* b) {
    asm volatile(
        "mma.sync.aligned.m16n8k8.row.col.f32.tf32.tf32.f32 "
        "{%0,%1,%2,%3},{%4,%5,%6,%7},{%8,%9},{%0,%1,%2,%3};"
        : "+f"(c[0]), "+f"(c[1]), "+f"(c[2]), "+f"(c[3])
        : "r"(a[0]), "r"(a[1]), "r"(a[2]), "r"(a[3]),
          "r"(b[0]), "r"(b[1]));
}

// ---------------------------------------------------------------------------
// GEMM: C[M,N] = A[M,K] @ B[K,N] + bias[N]. Row-major. M%128==0, N%128==0,
// K%16==0. 256 threads = 8 warps (4x2 warp grid), warp tile 32x64.
// smem holds tf32-converted tiles; strides padded for conflict-free frags.
// ---------------------------------------------------------------------------
#define GBM 128
#define GBN 128
#define GBK 16
#define SA  136   // 136 % 32 == 8 -> a-frag (k*SA + m) conflict-free
#define SBP 136   // b-frag (k*SBP + n) conflict-free

__global__ __launch_bounds__(256) void gemm_tf32(
    const float* __restrict__ A, const float* __restrict__ B,
    const float* __restrict__ bias, float* __restrict__ C,
    int M, int N, int K)
{
    __shared__ unsigned As[GBK * SA];   // As[k][m]
    __shared__ unsigned Bs[GBK * SBP];  // Bs[k][n]

    const int tid  = threadIdx.x;
    const int lane = tid & 31;
    const int warp = tid >> 5;
    const int wm   = warp & 3;     // 0..3
    const int wn   = warp >> 2;    // 0..1
    const int r    = lane >> 2;    // 0..7
    const int q    = lane & 3;     // 0..3
    const int bm   = blockIdx.y * GBM;
    const int bn   = blockIdx.x * GBN;

    // global load mapping (per BK slab: A 128x16, B 16x128, 2 float4 each)
    const int a_row = tid >> 2;           // 0..63
    const int a_kg  = (tid & 3) * 4;      // 0,4,8,12
    const int b_k   = tid >> 5;           // 0..7
    const int b_n   = (tid & 31) * 4;     // 0..124

    const float* Ap0 = A + (size_t)(bm + a_row) * K + a_kg;
    const float* Ap1 = Ap0 + (size_t)64 * K;
    const float* Bp0 = B + (size_t)b_k * N + bn + b_n;
    const float* Bp1 = Bp0 + (size_t)8 * N;

    float acc[2][8][4];
    #pragma unroll
    for (int i = 0; i < 2; i++)
        #pragma unroll
        for (int j = 0; j < 8; j++)
            #pragma unroll
            for (int k = 0; k < 4; k++) acc[i][j][k] = 0.0f;

    float4 pa0 = *(const float4*)Ap0;
    float4 pa1 = *(const float4*)Ap1;
    float4 pb0 = *(const float4*)Bp0;
    float4 pb1 = *(const float4*)Bp1;

    for (int k0 = 0; k0 < K; k0 += GBK) {
        // commit staged regs to smem (convert to tf32 once here)
        As[(a_kg + 0) * SA + a_row]      = f2tf32(pa0.x);
        As[(a_kg + 1) * SA + a_row]      = f2tf32(pa0.y);
        As[(a_kg + 2) * SA + a_row]      = f2tf32(pa0.z);
        As[(a_kg + 3) * SA + a_row]      = f2tf32(pa0.w);
        As[(a_kg + 0) * SA + a_row + 64] = f2tf32(pa1.x);
        As[(a_kg + 1) * SA + a_row + 64] = f2tf32(pa1.y);
        As[(a_kg + 2) * SA + a_row + 64] = f2tf32(pa1.z);
        As[(a_kg + 3) * SA + a_row + 64] = f2tf32(pa1.w);

        Bs[b_k * SBP + b_n + 0] = f2tf32(pb0.x);
        Bs[b_k * SBP + b_n + 1] = f2tf32(pb0.y);
        Bs[b_k * SBP + b_n + 2] = f2tf32(pb0.z);
        Bs[b_k * SBP + b_n + 3] = f2tf32(pb0.w);
        Bs[(b_k + 8) * SBP + b_n + 0] = f2tf32(pb1.x);
        Bs[(b_k + 8) * SBP + b_n + 1] = f2tf32(pb1.y);
        Bs[(b_k + 8) * SBP + b_n + 2] = f2tf32(pb1.z);
        Bs[(b_k + 8) * SBP + b_n + 3] = f2tf32(pb1.w);
        __syncthreads();

        if (k0 + GBK < K) {
            pa0 = *(const float4*)(Ap0 + k0 + GBK);
            pa1 = *(const float4*)(Ap1 + k0 + GBK);
            pb0 = *(const float4*)(Bp0 + (size_t)(k0 + GBK) * N);
            pb1 = *(const float4*)(Bp1 + (size_t)(k0 + GBK) * N);
        }

        #pragma unroll
        for (int kk = 0; kk < GBK; kk += 8) {
            unsigned af[2][4];
            #pragma unroll
            for (int mt = 0; mt < 2; mt++) {
                const int m = wm * 32 + mt * 16 + r;
                af[mt][0] = As[(kk + q) * SA + m];
                af[mt][1] = As[(kk + q) * SA + m + 8];
                af[mt][2] = As[(kk + q + 4) * SA + m];
                af[mt][3] = As[(kk + q + 4) * SA + m + 8];
            }
            #pragma unroll
            for (int nt = 0; nt < 8; nt++) {
                const int n = wn * 64 + nt * 8 + r;
                unsigned bf[2];
                bf[0] = Bs[(kk + q) * SBP + n];
                bf[1] = Bs[(kk + q + 4) * SBP + n];
                mma_tf32(acc[0][nt], af[0], bf);
                mma_tf32(acc[1][nt], af[1], bf);
            }
        }
        __syncthreads();
    }

    // epilogue: bias + store
    #pragma unroll
    for (int mt = 0; mt < 2; mt++) {
        const int row = bm + wm * 32 + mt * 16 + r;
        #pragma unroll
        for (int nt = 0; nt < 8; nt++) {
            const int col = bn + wn * 64 + nt * 8 + 2 * q;
            const float b0 = bias[col], b1 = bias[col + 1];
            float2 v0 = make_float2(acc[mt][nt][0] + b0, acc[mt][nt][1] + b1);
            float2 v1 = make_float2(acc[mt][nt][2] + b0, acc[mt][nt][3] + b1);
            *(float2*)(C + (size_t)row * N + col)       = v0;
            *(float2*)(C + (size_t)(row + 8) * N + col) = v1;
        }
    }
}

// ---------------------------------------------------------------------------
// Flash attention, tf32 mma. 128 threads = 4 warps; each warp owns 16 q rows;
// block = 64 q rows of one head. KV tiles of 64 rows staged as tf32 in smem.
// ---------------------------------------------------------------------------
#define SKS 68   // Ks[kvrow][dh]   : (n*SKS + k) frag conflict-free (68%32==4)
#define SVS 72   // Vs[kvrow][dh]   : (k*SVS + n) frag conflict-free (72%32==8)
#define SPS 68   // Ps[qrow][kv]    : (r*SPS + k) frag conflict-free
#define ATTN_SMEM_U32 (64 * SKS + 64 * SVS + 4 * 16 * SPS)
#define ATTN_SMEM_BYTES (ATTN_SMEM_U32 * 4)

__global__ __launch_bounds__(128) void attn_tf32(
    const float* __restrict__ qkv, float* __restrict__ attn_out)
{
    extern __shared__ unsigned sm[];
    unsigned* Ks = sm;                       // [64][SKS]
    unsigned* Vs = Ks + 64 * SKS;            // [64][SVS]

    const int h    = blockIdx.y;
    const int qb   = blockIdx.x;
    const int tid  = threadIdx.x;
    const int lane = tid & 31;
    const int warp = tid >> 5;
    const int r    = lane >> 2;   // 0..7
    const int q    = lane & 3;    // 0..3

    unsigned* Ps = Vs + 64 * SVS + warp * 16 * SPS;   // per-warp [16][SPS]

    // Q fragments, pre-scaled by 1/sqrt(64)=0.125, held in registers
    unsigned qa[8][4];
    const int qrow = qb * 64 + warp * 16 + r;
    const float* qp0 = qkv + (size_t)qrow * QKV_N + h * 64;
    const float* qp1 = qp0 + (size_t)8 * QKV_N;
    #pragma unroll
    for (int ks = 0; ks < 8; ks++) {
        qa[ks][0] = f2tf32(qp0[ks * 8 + q]     * 0.125f);
        qa[ks][1] = f2tf32(qp1[ks * 8 + q]     * 0.125f);
        qa[ks][2] = f2tf32(qp0[ks * 8 + q + 4] * 0.125f);
        qa[ks][3] = f2tf32(qp1[ks * 8 + q + 4] * 0.125f);
    }

    float o[8][4];
    #pragma unroll
    for (int nt = 0; nt < 8; nt++)
        #pragma unroll
        for (int i = 0; i < 4; i++) o[nt][i] = 0.0f;
    float m0 = -INFINITY, m1 = -INFINITY, l0 = 0.0f, l1 = 0.0f;

    #pragma unroll 1
    for (int kb = 0; kb < T_SEQ / 64; kb++) {
        __syncthreads();
        // stage K and V tiles (64x64 each), converting to tf32
        #pragma unroll 1
        for (int i = tid; i < 64 * 16; i += 128) {
            const int rr = i >> 4;
            const int c4 = (i & 15) * 4;
            const float* kp = qkv + (size_t)(kb * 64 + rr) * QKV_N + C_DIM + h * 64 + c4;
            float4 kx = *(const float4*)kp;
            float4 vx = *(const float4*)(kp + C_DIM);
            unsigned* kd = Ks + rr * SKS + c4;
            kd[0] = f2tf32(kx.x); kd[1] = f2tf32(kx.y);
            kd[2] = f2tf32(kx.z); kd[3] = f2tf32(kx.w);
            unsigned* vd = Vs + rr * SVS + c4;
            vd[0] = f2tf32(vx.x); vd[1] = f2tf32(vx.y);
            vd[2] = f2tf32(vx.z); vd[3] = f2tf32(vx.w);
        }
        __syncthreads();

        // S = Q @ K^T  (16 x 64 per warp)
        float s[8][4];
        #pragma unroll
        for (int nt = 0; nt < 8; nt++)
            #pragma unroll
            for (int i = 0; i < 4; i++) s[nt][i] = 0.0f;

        #pragma unroll
        for (int ks = 0; ks < 8; ks++) {
            #pragma unroll
            for (int nt = 0; nt < 8; nt++) {
                unsigned bf[2];
                bf[0] = Ks[(nt * 8 + r) * SKS + ks * 8 + q];
                bf[1] = Ks[(nt * 8 + r) * SKS + ks * 8 + q + 4];
                mma_tf32(s[nt], qa[ks], bf);
            }
        }

        // online softmax: row max (rows r0=row r, r1=row r+8 of warp tile)
        float mx0 = -INFINITY, mx1 = -INFINITY;
        #pragma unroll
        for (int nt = 0; nt < 8; nt++) {
            mx0 = fmaxf(mx0, fmaxf(s[nt][0], s[nt][1]));
            mx1 = fmaxf(mx1, fmaxf(s[nt][2], s[nt][3]));
        }
        #pragma unroll
        for (int off = 1; off < 4; off <<= 1) {
            mx0 = fmaxf(mx0, __shfl_xor_sync(0xffffffffu, mx0, off));
            mx1 = fmaxf(mx1, __shfl_xor_sync(0xffffffffu, mx1, off));
        }
        const float nm0 = fmaxf(m0, mx0);
        const float nm1 = fmaxf(m1, mx1);
        const float al0 = __expf(m0 - nm0);   // exp(-inf)=0 on first tile
        const float al1 = __expf(m1 - nm1);
        m0 = nm0; m1 = nm1;

        float rs0 = 0.0f, rs1 = 0.0f;
        __syncwarp();   // previous PV reads of Ps done before overwrite
        #pragma unroll
        for (int nt = 0; nt < 8; nt++) {
            const float p0 = __expf(s[nt][0] - m0);
            const float p1 = __expf(s[nt][1] - m0);
            const float p2 = __expf(s[nt][2] - m1);
            const float p3 = __expf(s[nt][3] - m1);
            rs0 += p0 + p1;
            rs1 += p2 + p3;
            uint2 u0 = make_uint2(f2tf32(p0), f2tf32(p1));
            uint2 u1 = make_uint2(f2tf32(p2), f2tf32(p3));
            *(uint2*)(Ps + r * SPS + nt * 8 + 2 * q)       = u0;
            *(uint2*)(Ps + (r + 8) * SPS + nt * 8 + 2 * q) = u1;
            o[nt][0] *= al0; o[nt][1] *= al0;
            o[nt][2] *= al1; o[nt][3] *= al1;
        }
        #pragma unroll
        for (int off = 1; off < 4; off <<= 1) {
            rs0 += __shfl_xor_sync(0xffffffffu, rs0, off);
            rs1 += __shfl_xor_sync(0xffffffffu, rs1, off);
        }
        l0 = l0 * al0 + rs0;
        l1 = l1 * al1 + rs1;
        __syncwarp();   // Ps writes visible to the whole warp

        // O += P @ V
        #pragma unroll
        for (int ks = 0; ks < 8; ks++) {
            unsigned af[4];
            af[0] = Ps[r * SPS + ks * 8 + q];
            af[1] = Ps[(r + 8) * SPS + ks * 8 + q];
            af[2] = Ps[r * SPS + ks * 8 + q + 4];
            af[3] = Ps[(r + 8) * SPS + ks * 8 + q + 4];
            #pragma unroll
            for (int nt = 0; nt < 8; nt++) {
                unsigned bf[2];
                bf[0] = Vs[(ks * 8 + q) * SVS + nt * 8 + r];
                bf[1] = Vs[(ks * 8 + q + 4) * SVS + nt * 8 + r];
                mma_tf32(o[nt], af, bf);
            }
        }
    }

    // normalize and store
    const float il0 = 1.0f / l0;
    const float il1 = 1.0f / l1;
    float* op0 = attn_out + (size_t)qrow * C_DIM + h * 64;
    float* op1 = op0 + (size_t)8 * C_DIM;
    #pragma unroll
    for (int nt = 0; nt < 8; nt++) {
        const int col = nt * 8 + 2 * q;
        *(float2*)(op0 + col) = make_float2(o[nt][0] * il0, o[nt][1] * il0);
        *(float2*)(op1 + col) = make_float2(o[nt][2] * il1, o[nt][3] * il1);
    }
}

// ---------------------------------------------------------------------------
extern "C" void kernel_launch(void* const* d_in, const int* in_sizes, int n_in,
                              void* d_out, int out_size)
{
    const float* x    = (const float*)d_in[0];
    const float* Wqkv = (const float*)d_in[1];
    const float* bqkv = (const float*)d_in[2];
    const float* Wout = (const float*)d_in[3];
    const float* bout = (const float*)d_in[4];
    float* out = (float*)d_out;

    float* qkv;
    float* attn;
    cudaGetSymbolAddress((void**)&qkv,  g_qkv);
    cudaGetSymbolAddress((void**)&attn, g_attn);

    cudaFuncSetAttribute(attn_tf32, cudaFuncAttributeMaxDynamicSharedMemorySize,
                         ATTN_SMEM_BYTES);

    // 1) QKV projection
    gemm_tf32<<<dim3(QKV_N / GBN, T_SEQ / GBM), 256>>>(
        x, Wqkv, bqkv, qkv, T_SEQ, QKV_N, C_DIM);

    // 2) Multi-head flash attention (tf32 tensor cores)
    attn_tf32<<<dim3(T_SEQ / 64, H_NUM), 128, ATTN_SMEM_BYTES>>>(qkv, attn);

    // 3) Output projection
    gemm_tf32<<<dim3(C_DIM / GBN, T_SEQ / GBM), 256>>>(
        attn, Wout, bout, out, T_SEQ, C_DIM, C_DIM);
}

// round 3
// speedup vs baseline: 4.9672x; 1.2071x over previous
#include <cuda_runtime.h>
#include <math.h>
#include <stdint.h>

#define T_SEQ   4096
#define C_DIM   1024
#define H_NUM   16
#define QKV_N   3072

// Scratch (device globals; allocation-free per harness rules)
__device__ float g_qkv[(size_t)T_SEQ * QKV_N];    // 48 MB (tf32 bits, Q pre-scaled)
__device__ float g_attn[(size_t)T_SEQ * C_DIM];   // 16 MB (tf32 bits)
__device__ float g_xc[(size_t)T_SEQ * C_DIM];     // 16 MB x as tf32 bits
__device__ float g_wqkvc[(size_t)C_DIM * QKV_N];  // 12 MB
__device__ float g_woutc[(size_t)C_DIM * C_DIM];  //  4 MB

__device__ __forceinline__ unsigned f2tf32(float x) {
    unsigned r;
    asm("cvt.rna.tf32.f32 %0, %1;" : "=r"(r) : "f"(x));
    return r;
}

__device__ __forceinline__ void mma_tf32(float* c, const unsigned* a, const unsigned* b) {
    asm volatile(
        "mma.sync.aligned.m16n8k8.row.col.f32.tf32.tf32.f32 "
        "{%0,%1,%2,%3},{%4,%5,%6,%7},{%8,%9},{%0,%1,%2,%3};"
        : "+f"(c[0]), "+f"(c[1]), "+f"(c[2]), "+f"(c[3])
        : "r"(a[0]), "r"(a[1]), "r"(a[2]), "r"(a[3]),
          "r"(b[0]), "r"(b[1]));
}

__device__ __forceinline__ void cp16(uint32_t dst, const void* src) {
    asm volatile("cp.async.cg.shared.global [%0], [%1], 16;" :: "r"(dst), "l"(src));
}
#define CP_COMMIT() asm volatile("cp.async.commit_group;" ::: "memory")

// ---------------------------------------------------------------------------
// Prepass: elementwise fp32 -> tf32 bits (vectorized)
// ---------------------------------------------------------------------------
__global__ __launch_bounds__(256) void cvt_tf32_kernel(
    const float4* __restrict__ in, float4* __restrict__ out, int n4)
{
    int i = blockIdx.x * 256 + threadIdx.x;
    if (i < n4) {
        float4 v = in[i];
        uint4 u;
        u.x = f2tf32(v.x); u.y = f2tf32(v.y);
        u.z = f2tf32(v.z); u.w = f2tf32(v.w);
        out[i] = *(float4*)&u;
    }
}

// ---------------------------------------------------------------------------
// GEMM: C[M,N] = A[M,K] @ B[K,N] + bias[N]. A,B hold tf32 bits already.
// 128x128x32 tile, 2-stage smem, 256 threads, warp tile 32x64.
// mode 1 = QKV epilogue (scale cols<1024 by 0.125, emit tf32 bits)
// mode 0 = plain fp32 output
// ---------------------------------------------------------------------------
#define GBM 128
#define GBN 128
#define GBK 32
#define SA  136
#define SBP 136
#define GEMM_STAGE_U32 (GBK * SA)           // per operand per stage
#define GEMM_SMEM_BYTES (4 * GEMM_STAGE_U32 * 2 * 4)

__global__ __launch_bounds__(256, 2) void gemm_tf32(
    const unsigned* __restrict__ A, const unsigned* __restrict__ B,
    const float* __restrict__ bias, float* __restrict__ C,
    int M, int N, int K, int mode)
{
    extern __shared__ unsigned gsm[];
    unsigned* As = gsm;                          // [2][GBK][SA]
    unsigned* Bs = gsm + 2 * GEMM_STAGE_U32;     // [2][GBK][SBP]

    const int tid  = threadIdx.x;
    const int lane = tid & 31;
    const int warp = tid >> 5;
    const int wm   = warp & 3;
    const int wn   = warp >> 2;
    const int r    = lane >> 2;
    const int q    = lane & 3;
    const int bm   = blockIdx.y * GBM;
    const int bn   = blockIdx.x * GBN;

    // global load mapping: A 128x32 (1024 f4), B 32x128 (1024 f4), 4 f4 each
    const int arow = tid >> 3;          // 0..31 (+ i*32)
    const int akg  = (tid & 7) * 4;     // 0,4,..,28
    const int bk   = tid >> 5;          // 0..7  (+ i*8)
    const int bn4  = (tid & 31) * 4;    // 0..124

    const unsigned* Ap = A + (size_t)(bm + arow) * K + akg;
    const unsigned* Bp = B + (size_t)bk * N + bn + bn4;

    float acc[2][8][4];
    #pragma unroll
    for (int i = 0; i < 2; i++)
        #pragma unroll
        for (int j = 0; j < 8; j++)
            #pragma unroll
            for (int k = 0; k < 4; k++) acc[i][j][k] = 0.0f;

    uint4 ra[4], rb[4];
    #pragma unroll
    for (int i = 0; i < 4; i++) {
        ra[i] = *(const uint4*)(Ap + (size_t)i * 32 * K);
        rb[i] = *(const uint4*)(Bp + (size_t)i * 8 * N);
    }
    // commit stage 0
    #pragma unroll
    for (int i = 0; i < 4; i++) {
        const int ar = arow + i * 32;
        As[(akg + 0) * SA + ar] = ra[i].x;
        As[(akg + 1) * SA + ar] = ra[i].y;
        As[(akg + 2) * SA + ar] = ra[i].z;
        As[(akg + 3) * SA + ar] = ra[i].w;
        *(uint4*)&Bs[(bk + i * 8) * SBP + bn4] = rb[i];
    }
    __syncthreads();

    int st = 0;
    for (int k0 = 0; k0 < K; k0 += GBK) {
        const bool has_next = (k0 + GBK) < K;
        if (has_next) {
            #pragma unroll
            for (int i = 0; i < 4; i++) {
                ra[i] = *(const uint4*)(Ap + (size_t)i * 32 * K + (k0 + GBK));
                rb[i] = *(const uint4*)(Bp + (size_t)(k0 + GBK + i * 8) * N);
            }
        }

        const unsigned* Asb = As + st * GEMM_STAGE_U32;
        const unsigned* Bsb = Bs + st * GEMM_STAGE_U32;
        #pragma unroll
        for (int kk = 0; kk < GBK; kk += 8) {
            unsigned af[2][4];
            #pragma unroll
            for (int mt = 0; mt < 2; mt++) {
                const int m = wm * 32 + mt * 16 + r;
                af[mt][0] = Asb[(kk + q) * SA + m];
                af[mt][1] = Asb[(kk + q) * SA + m + 8];
                af[mt][2] = Asb[(kk + q + 4) * SA + m];
                af[mt][3] = Asb[(kk + q + 4) * SA + m + 8];
            }
            #pragma unroll
            for (int nt = 0; nt < 8; nt++) {
                const int n = wn * 64 + nt * 8 + r;
                unsigned bf[2];
                bf[0] = Bsb[(kk + q) * SBP + n];
                bf[1] = Bsb[(kk + q + 4) * SBP + n];
                mma_tf32(acc[0][nt], af[0], bf);
                mma_tf32(acc[1][nt], af[1], bf);
            }
        }

        if (has_next) {
            unsigned* Asn = As + (st ^ 1) * GEMM_STAGE_U32;
            unsigned* Bsn = Bs + (st ^ 1) * GEMM_STAGE_U32;
            #pragma unroll
            for (int i = 0; i < 4; i++) {
                const int ar = arow + i * 32;
                Asn[(akg + 0) * SA + ar] = ra[i].x;
                Asn[(akg + 1) * SA + ar] = ra[i].y;
                Asn[(akg + 2) * SA + ar] = ra[i].z;
                Asn[(akg + 3) * SA + ar] = ra[i].w;
                *(uint4*)&Bsn[(bk + i * 8) * SBP + bn4] = rb[i];
            }
            __syncthreads();
            st ^= 1;
        }
    }

    // epilogue
    #pragma unroll
    for (int mt = 0; mt < 2; mt++) {
        const int row = bm + wm * 32 + mt * 16 + r;
        #pragma unroll
        for (int nt = 0; nt < 8; nt++) {
            const int col = bn + wn * 64 + nt * 8 + 2 * q;
            const float b0 = bias[col], b1 = bias[col + 1];
            float v00 = acc[mt][nt][0] + b0, v01 = acc[mt][nt][1] + b1;
            float v10 = acc[mt][nt][2] + b0, v11 = acc[mt][nt][3] + b1;
            if (mode == 1) {
                if (col < C_DIM) { v00 *= 0.125f; v01 *= 0.125f; v10 *= 0.125f; v11 *= 0.125f; }
                v00 = __uint_as_float(f2tf32(v00));
                v01 = __uint_as_float(f2tf32(v01));
                v10 = __uint_as_float(f2tf32(v10));
                v11 = __uint_as_float(f2tf32(v11));
            }
            *(float2*)(C + (size_t)row * N + col)       = make_float2(v00, v01);
            *(float2*)(C + (size_t)(row + 8) * N + col) = make_float2(v10, v11);
        }
    }
}

// ---------------------------------------------------------------------------
// Flash attention, tf32 mma, register-resident P (V rows permuted in-group:
// storage row j holds actual kv row {0,2,4,6,1,3,5,7}[j] of each 8-group).
// 128 threads = 4 warps x 16 q rows; KV tiles (64 rows) cp.async double-buffered.
// qkv holds tf32 bits with Q pre-scaled by 0.125.
// ---------------------------------------------------------------------------
#define AKS 68   // K tile stride (bank-clean frag loads; 272B rows, 16B mult)
#define AVS 72   // V tile stride (288B rows)
#define ATTN_TILE_K_U32 (64 * AKS)
#define ATTN_TILE_V_U32 (64 * AVS)
#define ATTN_SMEM_BYTES ((2 * ATTN_TILE_K_U32 + 2 * ATTN_TILE_V_U32) * 4)

__global__ __launch_bounds__(128, 3) void attn_tf32(
    const float* __restrict__ qkv_f, float* __restrict__ attn_out)
{
    extern __shared__ unsigned sm[];
    unsigned* Ksg = sm;                           // [2][64][AKS]
    unsigned* Vsg = sm + 2 * ATTN_TILE_K_U32;     // [2][64][AVS]
    const uint32_t ks_u = (uint32_t)__cvta_generic_to_shared(Ksg);
    const uint32_t vs_u = (uint32_t)__cvta_generic_to_shared(Vsg);

    const unsigned* qkv = (const unsigned*)qkv_f;

    const int h    = blockIdx.y;
    const int qb   = blockIdx.x;
    const int tid  = threadIdx.x;
    const int lane = tid & 31;
    const int warp = tid >> 5;
    const int r    = lane >> 2;
    const int q    = lane & 3;

    // Q fragments (already scaled + tf32 bits)
    unsigned qa[8][4];
    const int qrow = qb * 64 + warp * 16 + r;
    const unsigned* qp0 = qkv + (size_t)qrow * QKV_N + h * 64;
    const unsigned* qp1 = qp0 + (size_t)8 * QKV_N;
    #pragma unroll
    for (int ks = 0; ks < 8; ks++) {
        qa[ks][0] = qp0[ks * 8 + q];
        qa[ks][1] = qp1[ks * 8 + q];
        qa[ks][2] = qp0[ks * 8 + q + 4];
        qa[ks][3] = qp1[ks * 8 + q + 4];
    }

    float o[8][4];
    #pragma unroll
    for (int nt = 0; nt < 8; nt++)
        #pragma unroll
        for (int i = 0; i < 4; i++) o[nt][i] = 0.0f;
    float m0 = -INFINITY, m1 = -INFINITY, l0 = 0.0f, l1 = 0.0f;

    // stage lambda: cp.async one KV tile into buffer buf
    auto stage = [&](int kb, int buf) {
        const unsigned* kbase = qkv + (size_t)(kb * 64) * QKV_N + C_DIM + h * 64;
        const uint32_t kd = ks_u + (uint32_t)buf * ATTN_TILE_K_U32 * 4;
        const uint32_t vd = vs_u + (uint32_t)buf * ATTN_TILE_V_U32 * 4;
        #pragma unroll
        for (int i = 0; i < 8; i++) {
            const int idx = tid + i * 128;
            const int row = idx >> 4;
            const int c4  = (idx & 15) * 4;
            cp16(kd + (uint32_t)(row * AKS + c4) * 4,
                 kbase + (size_t)row * QKV_N + c4);
            const int j = row & 7;
            const int prow = (row & ~7) | ((j < 4) ? 2 * j : 2 * j - 7);
            cp16(vd + (uint32_t)(row * AVS + c4) * 4,
                 kbase + C_DIM + (size_t)prow * QKV_N + c4);
        }
    };

    stage(0, 0);
    CP_COMMIT();

    #pragma unroll 1
    for (int kb = 0; kb < T_SEQ / 64; kb++) {
        const int cur = kb & 1;
        const bool has_next = (kb + 1) < T_SEQ / 64;
        if (has_next) {
            stage(kb + 1, cur ^ 1);
            CP_COMMIT();
            asm volatile("cp.async.wait_group 1;" ::: "memory");
        } else {
            asm volatile("cp.async.wait_group 0;" ::: "memory");
        }
        __syncthreads();

        const unsigned* Ks = Ksg + cur * ATTN_TILE_K_U32;
        const unsigned* Vs = Vsg + cur * ATTN_TILE_V_U32;

        // S = Q @ K^T (16x64 per warp), P kept in registers
        float p[8][4];
        #pragma unroll
        for (int nt = 0; nt < 8; nt++)
            #pragma unroll
            for (int i = 0; i < 4; i++) p[nt][i] = 0.0f;

        #pragma unroll
        for (int ks = 0; ks < 8; ks++) {
            #pragma unroll
            for (int nt = 0; nt < 8; nt++) {
                unsigned bf[2];
                bf[0] = Ks[(nt * 8 + r) * AKS + ks * 8 + q];
                bf[1] = Ks[(nt * 8 + r) * AKS + ks * 8 + q + 4];
                mma_tf32(p[nt], qa[ks], bf);
            }
        }

        // online softmax
        float mx0 = -INFINITY, mx1 = -INFINITY;
        #pragma unroll
        for (int nt = 0; nt < 8; nt++) {
            mx0 = fmaxf(mx0, fmaxf(p[nt][0], p[nt][1]));
            mx1 = fmaxf(mx1, fmaxf(p[nt][2], p[nt][3]));
        }
        #pragma unroll
        for (int off = 1; off < 4; off <<= 1) {
            mx0 = fmaxf(mx0, __shfl_xor_sync(0xffffffffu, mx0, off));
            mx1 = fmaxf(mx1, __shfl_xor_sync(0xffffffffu, mx1, off));
        }
        const float nm0 = fmaxf(m0, mx0);
        const float nm1 = fmaxf(m1, mx1);
        const float al0 = __expf(m0 - nm0);
        const float al1 = __expf(m1 - nm1);
        m0 = nm0; m1 = nm1;

        float rs0 = 0.0f, rs1 = 0.0f;
        #pragma unroll
        for (int nt = 0; nt < 8; nt++) {
            p[nt][0] = __expf(p[nt][0] - m0);
            p[nt][1] = __expf(p[nt][1] - m0);
            p[nt][2] = __expf(p[nt][2] - m1);
            p[nt][3] = __expf(p[nt][3] - m1);
            rs0 += p[nt][0] + p[nt][1];
            rs1 += p[nt][2] + p[nt][3];
            o[nt][0] *= al0; o[nt][1] *= al0;
            o[nt][2] *= al1; o[nt][3] *= al1;
        }
        #pragma unroll
        for (int off = 1; off < 4; off <<= 1) {
            rs0 += __shfl_xor_sync(0xffffffffu, rs0, off);
            rs1 += __shfl_xor_sync(0xffffffffu, rs1, off);
        }
        l0 = l0 * al0 + rs0;
        l1 = l1 * al1 + rs1;

        // O += P @ V  (A-frag = S-frag layout thanks to V row permutation)
        #pragma unroll
        for (int g = 0; g < 8; g++) {
            unsigned af[4];
            af[0] = f2tf32(p[g][0]);
            af[1] = f2tf32(p[g][2]);
            af[2] = f2tf32(p[g][1]);
            af[3] = f2tf32(p[g][3]);
            #pragma unroll
            for (int nt = 0; nt < 8; nt++) {
                unsigned bf[2];
                bf[0] = Vs[(g * 8 + q) * AVS + nt * 8 + r];
                bf[1] = Vs[(g * 8 + q + 4) * AVS + nt * 8 + r];
                mma_tf32(o[nt], af, bf);
            }
        }
        __syncthreads();
    }

    // normalize, tf32-round (out-proj consumes tf32 bits), store
    const float il0 = 1.0f / l0;
    const float il1 = 1.0f / l1;
    float* op0 = attn_out + (size_t)qrow * C_DIM + h * 64;
    float* op1 = op0 + (size_t)8 * C_DIM;
    #pragma unroll
    for (int nt = 0; nt < 8; nt++) {
        const int col = nt * 8 + 2 * q;
        *(float2*)(op0 + col) = make_float2(
            __uint_as_float(f2tf32(o[nt][0] * il0)),
            __uint_as_float(f2tf32(o[nt][1] * il0)));
        *(float2*)(op1 + col) = make_float2(
            __uint_as_float(f2tf32(o[nt][2] * il1)),
            __uint_as_float(f2tf32(o[nt][3] * il1)));
    }
}

// ---------------------------------------------------------------------------
extern "C" void kernel_launch(void* const* d_in, const int* in_sizes, int n_in,
                              void* d_out, int out_size)
{
    const float* x    = (const float*)d_in[0];
    const float* Wqkv = (const float*)d_in[1];
    const float* bqkv = (const float*)d_in[2];
    const float* Wout = (const float*)d_in[3];
    const float* bout = (const float*)d_in[4];
    float* out = (float*)d_out;

    float *qkv, *attn, *xc, *wqkvc, *woutc;
    cudaGetSymbolAddress((void**)&qkv,   g_qkv);
    cudaGetSymbolAddress((void**)&attn,  g_attn);
    cudaGetSymbolAddress((void**)&xc,    g_xc);
    cudaGetSymbolAddress((void**)&wqkvc, g_wqkvc);
    cudaGetSymbolAddress((void**)&woutc, g_woutc);

    cudaFuncSetAttribute(gemm_tf32, cudaFuncAttributeMaxDynamicSharedMemorySize,
                         GEMM_SMEM_BYTES);
    cudaFuncSetAttribute(attn_tf32, cudaFuncAttributeMaxDynamicSharedMemorySize,
                         ATTN_SMEM_BYTES);

    // 0) prepass: fp32 -> tf32 bits
    const int n4x = T_SEQ * C_DIM / 4;
    const int n4w = C_DIM * QKV_N / 4;
    const int n4o = C_DIM * C_DIM / 4;
    cvt_tf32_kernel<<<(n4x + 255) / 256, 256>>>((const float4*)x,    (float4*)xc,    n4x);
    cvt_tf32_kernel<<<(n4w + 255) / 256, 256>>>((const float4*)Wqkv, (float4*)wqkvc, n4w);
    cvt_tf32_kernel<<<(n4o + 255) / 256, 256>>>((const float4*)Wout, (float4*)woutc, n4o);

    // 1) QKV projection (epilogue: bias, Q*0.125, tf32-round)
    gemm_tf32<<<dim3(QKV_N / GBN, T_SEQ / GBM), 256, GEMM_SMEM_BYTES>>>(
        (const unsigned*)xc, (const unsigned*)wqkvc, bqkv, qkv,
        T_SEQ, QKV_N, C_DIM, 1);

    // 2) Multi-head flash attention (register P, cp.async KV)
    attn_tf32<<<dim3(T_SEQ / 64, H_NUM), 128, ATTN_SMEM_BYTES>>>(qkv, attn);

    // 3) Output projection (plain fp32 epilogue)
    gemm_tf32<<<dim3(C_DIM / GBN, T_SEQ / GBM), 256, GEMM_SMEM_BYTES>>>(
        (const unsigned*)attn, (const unsigned*)woutc, bout, out,
        T_SEQ, C_DIM, C_DIM, 0);
}

// round 4
// speedup vs baseline: 6.0189x; 1.2117x over previous
#include <cuda_runtime.h>
#include <math.h>
#include <stdint.h>

#define T_SEQ   4096
#define C_DIM   1024
#define H_NUM   16
#define QKV_N   3072

// Scratch (device globals; allocation-free per harness rules)
__device__ float g_qkv[(size_t)T_SEQ * QKV_N];    // 48 MB (tf32 bits, Q pre-scaled)
__device__ float g_attn[(size_t)T_SEQ * C_DIM];   // 16 MB (tf32 bits)
__device__ float g_xc[(size_t)T_SEQ * C_DIM];     // 16 MB x as tf32 bits
__device__ float g_wqkvc[(size_t)C_DIM * QKV_N];  // 12 MB
__device__ float g_woutc[(size_t)C_DIM * C_DIM];  //  4 MB

__device__ __forceinline__ unsigned f2tf32(float x) {
    unsigned r;
    asm("cvt.rna.tf32.f32 %0, %1;" : "=r"(r) : "f"(x));
    return r;
}

__device__ __forceinline__ void mma_tf32(float* c, const unsigned* a, const unsigned* b) {
    asm volatile(
        "mma.sync.aligned.m16n8k8.row.col.f32.tf32.tf32.f32 "
        "{%0,%1,%2,%3},{%4,%5,%6,%7},{%8,%9},{%0,%1,%2,%3};"
        : "+f"(c[0]), "+f"(c[1]), "+f"(c[2]), "+f"(c[3])
        : "r"(a[0]), "r"(a[1]), "r"(a[2]), "r"(a[3]),
          "r"(b[0]), "r"(b[1]));
}

__device__ __forceinline__ void cp16(uint32_t dst, const void* src) {
    asm volatile("cp.async.cg.shared.global [%0], [%1], 16;" :: "r"(dst), "l"(src));
}
#define CP_COMMIT() asm volatile("cp.async.commit_group;" ::: "memory")

// ---------------------------------------------------------------------------
// Prepass: elementwise fp32 -> tf32 bits (vectorized)
// ---------------------------------------------------------------------------
__global__ __launch_bounds__(256) void cvt_tf32_kernel(
    const float4* __restrict__ in, float4* __restrict__ out, int n4)
{
    int i = blockIdx.x * 256 + threadIdx.x;
    if (i < n4) {
        float4 v = in[i];
        uint4 u;
        u.x = f2tf32(v.x); u.y = f2tf32(v.y);
        u.z = f2tf32(v.z); u.w = f2tf32(v.w);
        out[i] = *(float4*)&u;
    }
}

// ---------------------------------------------------------------------------
// GEMM: C[M,N] = A[M,K] @ B[K,N] + bias[N]. A,B hold tf32 bits already.
// 128x128 tile, BK=16, 4-stage cp.async pipeline, 256 threads, warp tile
// 32x64. K % 16 == 0. mode 1 = QKV epilogue (scale cols<1024 by 0.125, emit
// tf32 bits), mode 0 = plain fp32 output.
// ---------------------------------------------------------------------------
#define GBM 128
#define GBN 128
#define GBK 16
#define SAP 20          // A stage row stride (u32): [128][20], bank-clean
#define SBP 136         // B stage row stride (u32): [16][136], bank-clean
#define STAGE_A (GBM * SAP)       // 2560 u32
#define STAGE_B (GBK * SBP)       // 2176 u32
#define GEMM_NSTAGE 4
#define GEMM_SMEM_BYTES ((GEMM_NSTAGE * (STAGE_A + STAGE_B)) * 4)   // 75776 B

__global__ __launch_bounds__(256, 2) void gemm_tf32(
    const unsigned* __restrict__ A, const unsigned* __restrict__ B,
    const float* __restrict__ bias, float* __restrict__ C,
    int M, int N, int K, int mode)
{
    extern __shared__ unsigned gsm[];
    unsigned* As = gsm;                                 // [4][128][SAP]
    unsigned* Bs = gsm + GEMM_NSTAGE * STAGE_A;         // [4][16][SBP]
    const uint32_t as_u = (uint32_t)__cvta_generic_to_shared(As);
    const uint32_t bs_u = (uint32_t)__cvta_generic_to_shared(Bs);

    const int tid  = threadIdx.x;
    const int lane = tid & 31;
    const int warp = tid >> 5;
    const int wm   = warp & 3;
    const int wn   = warp >> 2;
    const int r    = lane >> 2;
    const int q    = lane & 3;
    const int bm   = blockIdx.y * GBM;
    const int bn   = blockIdx.x * GBN;

    // cp.async mapping: A tile 128x16 = 512 x 16B chunks; B tile 16x128 = 512
    const int a_m  = tid >> 1;            // chunk c=tid+i*256: m = c>>2 -> do 2 chunks
    // chunk0: c = tid        -> m = tid>>2,        kg = (tid&3)*4
    // chunk1: c = tid + 256  -> m = (tid>>2) + 64, kg same
    const int am0 = tid >> 2;
    const int akg = (tid & 3) * 4;
    const int bk0 = tid >> 5;             // chunk0 k, chunk1 k = +8
    const int bn4 = (tid & 31) * 4;
    (void)a_m;

    const unsigned* Ag0 = A + (size_t)(bm + am0) * K + akg;
    const unsigned* Ag1 = A + (size_t)(bm + am0 + 64) * K + akg;
    const unsigned* Bg0 = B + (size_t)bk0 * N + bn + bn4;
    const unsigned* Bg1 = B + (size_t)(bk0 + 8) * N + bn + bn4;

    const int nslab = K / GBK;

    auto stage = [&](int slab) {
        const int buf = slab & 3;
        const uint32_t ad = as_u + (uint32_t)(buf * STAGE_A) * 4;
        const uint32_t bd = bs_u + (uint32_t)(buf * STAGE_B) * 4;
        const int koff = slab * GBK;
        cp16(ad + (uint32_t)(am0 * SAP + akg) * 4,        Ag0 + koff);
        cp16(ad + (uint32_t)((am0 + 64) * SAP + akg) * 4, Ag1 + koff);
        cp16(bd + (uint32_t)(bk0 * SBP + bn4) * 4,        Bg0 + (size_t)koff * N);
        cp16(bd + (uint32_t)((bk0 + 8) * SBP + bn4) * 4,  Bg1 + (size_t)koff * N);
        CP_COMMIT();
    };

    float acc[2][8][4];
    #pragma unroll
    for (int i = 0; i < 2; i++)
        #pragma unroll
        for (int j = 0; j < 8; j++)
            #pragma unroll
            for (int k = 0; k < 4; k++) acc[i][j][k] = 0.0f;

    stage(0); stage(1); stage(2);

    #pragma unroll 1
    for (int i = 0; i < nslab; i++) {
        if (i + 2 < nslab) {
            asm volatile("cp.async.wait_group 2;" ::: "memory");
        } else {
            asm volatile("cp.async.wait_group 0;" ::: "memory");
        }
        __syncthreads();

        if (i + 3 < nslab) stage(i + 3);

        const int buf = i & 3;
        const unsigned* Asb = As + buf * STAGE_A;
        const unsigned* Bsb = Bs + buf * STAGE_B;

        #pragma unroll
        for (int kk = 0; kk < GBK; kk += 8) {
            unsigned af[2][4];
            #pragma unroll
            for (int mt = 0; mt < 2; mt++) {
                const int m = wm * 32 + mt * 16 + r;
                af[mt][0] = Asb[m * SAP + kk + q];
                af[mt][1] = Asb[(m + 8) * SAP + kk + q];
                af[mt][2] = Asb[m * SAP + kk + q + 4];
                af[mt][3] = Asb[(m + 8) * SAP + kk + q + 4];
            }
            #pragma unroll
            for (int nt = 0; nt < 8; nt++) {
                const int n = wn * 64 + nt * 8 + r;
                unsigned bf[2];
                bf[0] = Bsb[(kk + q) * SBP + n];
                bf[1] = Bsb[(kk + q + 4) * SBP + n];
                mma_tf32(acc[0][nt], af[0], bf);
                mma_tf32(acc[1][nt], af[1], bf);
            }
        }
        __syncthreads();
    }

    // epilogue
    #pragma unroll
    for (int mt = 0; mt < 2; mt++) {
        const int row = bm + wm * 32 + mt * 16 + r;
        #pragma unroll
        for (int nt = 0; nt < 8; nt++) {
            const int col = bn + wn * 64 + nt * 8 + 2 * q;
            const float b0 = bias[col], b1 = bias[col + 1];
            float v00 = acc[mt][nt][0] + b0, v01 = acc[mt][nt][1] + b1;
            float v10 = acc[mt][nt][2] + b0, v11 = acc[mt][nt][3] + b1;
            if (mode == 1) {
                if (col < C_DIM) { v00 *= 0.125f; v01 *= 0.125f; v10 *= 0.125f; v11 *= 0.125f; }
                v00 = __uint_as_float(f2tf32(v00));
                v01 = __uint_as_float(f2tf32(v01));
                v10 = __uint_as_float(f2tf32(v10));
                v11 = __uint_as_float(f2tf32(v11));
            }
            *(float2*)(C + (size_t)row * N + col)       = make_float2(v00, v01);
            *(float2*)(C + (size_t)(row + 8) * N + col) = make_float2(v10, v11);
        }
    }
}

// ---------------------------------------------------------------------------
// Flash attention, tf32 mma, register-resident P (V rows permuted in-group:
// storage row j holds actual kv row {0,2,4,6,1,3,5,7}[j] of each 8-group).
// 128 threads = 4 warps x 16 q rows; KV tiles (64 rows) cp.async double-buffered.
// qkv holds tf32 bits with Q pre-scaled by 0.125.
// ---------------------------------------------------------------------------
#define AKS 68
#define AVS 72
#define ATTN_TILE_K_U32 (64 * AKS)
#define ATTN_TILE_V_U32 (64 * AVS)
#define ATTN_SMEM_BYTES ((2 * ATTN_TILE_K_U32 + 2 * ATTN_TILE_V_U32) * 4)

__global__ __launch_bounds__(128, 3) void attn_tf32(
    const float* __restrict__ qkv_f, float* __restrict__ attn_out)
{
    extern __shared__ unsigned sm[];
    unsigned* Ksg = sm;                           // [2][64][AKS]
    unsigned* Vsg = sm + 2 * ATTN_TILE_K_U32;     // [2][64][AVS]
    const uint32_t ks_u = (uint32_t)__cvta_generic_to_shared(Ksg);
    const uint32_t vs_u = (uint32_t)__cvta_generic_to_shared(Vsg);

    const unsigned* qkv = (const unsigned*)qkv_f;

    const int h    = blockIdx.y;
    const int qb   = blockIdx.x;
    const int tid  = threadIdx.x;
    const int lane = tid & 31;
    const int warp = tid >> 5;
    const int r    = lane >> 2;
    const int q    = lane & 3;

    // Q fragments (already scaled + tf32 bits)
    unsigned qa[8][4];
    const int qrow = qb * 64 + warp * 16 + r;
    const unsigned* qp0 = qkv + (size_t)qrow * QKV_N + h * 64;
    const unsigned* qp1 = qp0 + (size_t)8 * QKV_N;
    #pragma unroll
    for (int ks = 0; ks < 8; ks++) {
        qa[ks][0] = qp0[ks * 8 + q];
        qa[ks][1] = qp1[ks * 8 + q];
        qa[ks][2] = qp0[ks * 8 + q + 4];
        qa[ks][3] = qp1[ks * 8 + q + 4];
    }

    float o[8][4];
    #pragma unroll
    for (int nt = 0; nt < 8; nt++)
        #pragma unroll
        for (int i = 0; i < 4; i++) o[nt][i] = 0.0f;
    float m0 = -INFINITY, m1 = -INFINITY, l0 = 0.0f, l1 = 0.0f;

    auto stage = [&](int kb, int buf) {
        const unsigned* kbase = qkv + (size_t)(kb * 64) * QKV_N + C_DIM + h * 64;
        const uint32_t kd = ks_u + (uint32_t)buf * ATTN_TILE_K_U32 * 4;
        const uint32_t vd = vs_u + (uint32_t)buf * ATTN_TILE_V_U32 * 4;
        #pragma unroll
        for (int i = 0; i < 8; i++) {
            const int idx = tid + i * 128;
            const int row = idx >> 4;
            const int c4  = (idx & 15) * 4;
            cp16(kd + (uint32_t)(row * AKS + c4) * 4,
                 kbase + (size_t)row * QKV_N + c4);
            const int j = row & 7;
            const int prow = (row & ~7) | ((j < 4) ? 2 * j : 2 * j - 7);
            cp16(vd + (uint32_t)(row * AVS + c4) * 4,
                 kbase + C_DIM + (size_t)prow * QKV_N + c4);
        }
    };

    stage(0, 0);
    CP_COMMIT();

    #pragma unroll 1
    for (int kb = 0; kb < T_SEQ / 64; kb++) {
        const int cur = kb & 1;
        const bool has_next = (kb + 1) < T_SEQ / 64;
        if (has_next) {
            stage(kb + 1, cur ^ 1);
            CP_COMMIT();
            asm volatile("cp.async.wait_group 1;" ::: "memory");
        } else {
            asm volatile("cp.async.wait_group 0;" ::: "memory");
        }
        __syncthreads();

        const unsigned* Ks = Ksg + cur * ATTN_TILE_K_U32;
        const unsigned* Vs = Vsg + cur * ATTN_TILE_V_U32;

        // S = Q @ K^T (16x64 per warp), P kept in registers
        float p[8][4];
        #pragma unroll
        for (int nt = 0; nt < 8; nt++)
            #pragma unroll
            for (int i = 0; i < 4; i++) p[nt][i] = 0.0f;

        #pragma unroll
        for (int ks = 0; ks < 8; ks++) {
            #pragma unroll
            for (int nt = 0; nt < 8; nt++) {
                unsigned bf[2];
                bf[0] = Ks[(nt * 8 + r) * AKS + ks * 8 + q];
                bf[1] = Ks[(nt * 8 + r) * AKS + ks * 8 + q + 4];
                mma_tf32(p[nt], qa[ks], bf);
            }
        }

        // online softmax
        float mx0 = -INFINITY, mx1 = -INFINITY;
        #pragma unroll
        for (int nt = 0; nt < 8; nt++) {
            mx0 = fmaxf(mx0, fmaxf(p[nt][0], p[nt][1]));
            mx1 = fmaxf(mx1, fmaxf(p[nt][2], p[nt][3]));
        }
        #pragma unroll
        for (int off = 1; off < 4; off <<= 1) {
            mx0 = fmaxf(mx0, __shfl_xor_sync(0xffffffffu, mx0, off));
            mx1 = fmaxf(mx1, __shfl_xor_sync(0xffffffffu, mx1, off));
        }
        const float nm0 = fmaxf(m0, mx0);
        const float nm1 = fmaxf(m1, mx1);
        const float al0 = __expf(m0 - nm0);
        const float al1 = __expf(m1 - nm1);
        m0 = nm0; m1 = nm1;

        float rs0 = 0.0f, rs1 = 0.0f;
        #pragma unroll
        for (int nt = 0; nt < 8; nt++) {
            p[nt][0] = __expf(p[nt][0] - m0);
            p[nt][1] = __expf(p[nt][1] - m0);
            p[nt][2] = __expf(p[nt][2] - m1);
            p[nt][3] = __expf(p[nt][3] - m1);
            rs0 += p[nt][0] + p[nt][1];
            rs1 += p[nt][2] + p[nt][3];
            o[nt][0] *= al0; o[nt][1] *= al0;
            o[nt][2] *= al1; o[nt][3] *= al1;
        }
        #pragma unroll
        for (int off = 1; off < 4; off <<= 1) {
            rs0 += __shfl_xor_sync(0xffffffffu, rs0, off);
            rs1 += __shfl_xor_sync(0xffffffffu, rs1, off);
        }
        l0 = l0 * al0 + rs0;
        l1 = l1 * al1 + rs1;

        // O += P @ V  (A-frag = S-frag layout thanks to V row permutation)
        #pragma unroll
        for (int g = 0; g < 8; g++) {
            unsigned af[4];
            af[0] = f2tf32(p[g][0]);
            af[1] = f2tf32(p[g][2]);
            af[2] = f2tf32(p[g][1]);
            af[3] = f2tf32(p[g][3]);
            #pragma unroll
            for (int nt = 0; nt < 8; nt++) {
                unsigned bf[2];
                bf[0] = Vs[(g * 8 + q) * AVS + nt * 8 + r];
                bf[1] = Vs[(g * 8 + q + 4) * AVS + nt * 8 + r];
                mma_tf32(o[nt], af, bf);
            }
        }
        __syncthreads();
    }

    // normalize, tf32-round (out-proj consumes tf32 bits), store
    const float il0 = 1.0f / l0;
    const float il1 = 1.0f / l1;
    float* op0 = attn_out + (size_t)qrow * C_DIM + h * 64;
    float* op1 = op0 + (size_t)8 * C_DIM;
    #pragma unroll
    for (int nt = 0; nt < 8; nt++) {
        const int col = nt * 8 + 2 * q;
        *(float2*)(op0 + col) = make_float2(
            __uint_as_float(f2tf32(o[nt][0] * il0)),
            __uint_as_float(f2tf32(o[nt][1] * il0)));
        *(float2*)(op1 + col) = make_float2(
            __uint_as_float(f2tf32(o[nt][2] * il1)),
            __uint_as_float(f2tf32(o[nt][3] * il1)));
    }
}

// ---------------------------------------------------------------------------
extern "C" void kernel_launch(void* const* d_in, const int* in_sizes, int n_in,
                              void* d_out, int out_size)
{
    const float* x    = (const float*)d_in[0];
    const float* Wqkv = (const float*)d_in[1];
    const float* bqkv = (const float*)d_in[2];
    const float* Wout = (const float*)d_in[3];
    const float* bout = (const float*)d_in[4];
    float* out = (float*)d_out;

    float *qkv, *attn, *xc, *wqkvc, *woutc;
    cudaGetSymbolAddress((void**)&qkv,   g_qkv);
    cudaGetSymbolAddress((void**)&attn,  g_attn);
    cudaGetSymbolAddress((void**)&xc,    g_xc);
    cudaGetSymbolAddress((void**)&wqkvc, g_wqkvc);
    cudaGetSymbolAddress((void**)&woutc, g_woutc);

    cudaFuncSetAttribute(gemm_tf32, cudaFuncAttributeMaxDynamicSharedMemorySize,
                         GEMM_SMEM_BYTES);
    cudaFuncSetAttribute(attn_tf32, cudaFuncAttributeMaxDynamicSharedMemorySize,
                         ATTN_SMEM_BYTES);

    // 0) prepass: fp32 -> tf32 bits
    const int n4x = T_SEQ * C_DIM / 4;
    const int n4w = C_DIM * QKV_N / 4;
    const int n4o = C_DIM * C_DIM / 4;
    cvt_tf32_kernel<<<(n4x + 255) / 256, 256>>>((const float4*)x,    (float4*)xc,    n4x);
    cvt_tf32_kernel<<<(n4w + 255) / 256, 256>>>((const float4*)Wqkv, (float4*)wqkvc, n4w);
    cvt_tf32_kernel<<<(n4o + 255) / 256, 256>>>((const float4*)Wout, (float4*)woutc, n4o);

    // 1) QKV projection (epilogue: bias, Q*0.125, tf32-round)
    gemm_tf32<<<dim3(QKV_N / GBN, T_SEQ / GBM), 256, GEMM_SMEM_BYTES>>>(
        (const unsigned*)xc, (const unsigned*)wqkvc, bqkv, qkv,
        T_SEQ, QKV_N, C_DIM, 1);

    // 2) Multi-head flash attention (register P, cp.async KV)
    attn_tf32<<<dim3(T_SEQ / 64, H_NUM), 128, ATTN_SMEM_BYTES>>>(qkv, attn);

    // 3) Output projection (plain fp32 epilogue)
    gemm_tf32<<<dim3(C_DIM / GBN, T_SEQ / GBM), 256, GEMM_SMEM_BYTES>>>(
        (const unsigned*)attn, (const unsigned*)woutc, bout, out,
        T_SEQ, C_DIM, C_DIM, 0);
}

// round 6
// speedup vs baseline: 7.7993x; 1.2958x over previous
#include <cuda_runtime.h>
#include <cuda_fp16.h>
#include <math.h>
#include <stdint.h>

#define T_SEQ   4096
#define C_DIM   1024
#define H_NUM   16
#define QKV_N   3072

// Scratch (device globals; allocation-free per harness rules)
__device__ __half g_qh[(size_t)T_SEQ * C_DIM];          // 8 MB Q fp16 (pre-scaled)
__device__ __half g_kh[(size_t)T_SEQ * C_DIM];          // 8 MB K fp16
__device__ __half g_vt[(size_t)H_NUM * 64 * T_SEQ];     // 8 MB V fp16, [h][dh][T]
__device__ float  g_attn[(size_t)T_SEQ * C_DIM];        // 16 MB (tf32 bits)
__device__ float  g_xc[(size_t)T_SEQ * C_DIM];          // 16 MB x as tf32 bits
__device__ float  g_wqkvc[(size_t)C_DIM * QKV_N];       // 12 MB
__device__ float  g_woutc[(size_t)C_DIM * C_DIM];       //  4 MB

__device__ __forceinline__ unsigned f2tf32(float x) {
    unsigned r;
    asm("cvt.rna.tf32.f32 %0, %1;" : "=r"(r) : "f"(x));
    return r;
}

__device__ __forceinline__ void mma_tf32(float* c, const unsigned* a, const unsigned* b) {
    asm volatile(
        "mma.sync.aligned.m16n8k8.row.col.f32.tf32.tf32.f32 "
        "{%0,%1,%2,%3},{%4,%5,%6,%7},{%8,%9},{%0,%1,%2,%3};"
        : "+f"(c[0]), "+f"(c[1]), "+f"(c[2]), "+f"(c[3])
        : "r"(a[0]), "r"(a[1]), "r"(a[2]), "r"(a[3]),
          "r"(b[0]), "r"(b[1]));
}

__device__ __forceinline__ void mma_f16(float* c, const unsigned* a, const unsigned* b) {
    asm volatile(
        "mma.sync.aligned.m16n8k16.row.col.f32.f16.f16.f32 "
        "{%0,%1,%2,%3},{%4,%5,%6,%7},{%8,%9},{%0,%1,%2,%3};"
        : "+f"(c[0]), "+f"(c[1]), "+f"(c[2]), "+f"(c[3])
        : "r"(a[0]), "r"(a[1]), "r"(a[2]), "r"(a[3]),
          "r"(b[0]), "r"(b[1]));
}

__device__ __forceinline__ void cp16(uint32_t dst, const void* src) {
    asm volatile("cp.async.cg.shared.global [%0], [%1], 16;" :: "r"(dst), "l"(src));
}
#define CP_COMMIT() asm volatile("cp.async.commit_group;" ::: "memory")

// ---------------------------------------------------------------------------
// Prepass: elementwise fp32 -> tf32 bits (vectorized)
// ---------------------------------------------------------------------------
__global__ __launch_bounds__(256) void cvt_tf32_kernel(
    const float4* __restrict__ in, float4* __restrict__ out, int n4)
{
    int i = blockIdx.x * 256 + threadIdx.x;
    if (i < n4) {
        float4 v = in[i];
        uint4 u;
        u.x = f2tf32(v.x); u.y = f2tf32(v.y);
        u.z = f2tf32(v.z); u.w = f2tf32(v.w);
        out[i] = *(float4*)&u;
    }
}

// ---------------------------------------------------------------------------
// GEMM: tf32 mma, 128x128 tile, BK=16, 4-stage cp.async, 256 threads.
// mode 0: C = A@B + bias (fp32 out)
// mode 1: QKV epilogue -> split fp16 outputs:
//   cols [0,1024):    Q*0.125 -> qh[row][col]
//   cols [1024,2048): K       -> kh[row][col-1024]
//   cols [2048,3072): V       -> vt[(col-2048)][row]  (head-transposed)
// ---------------------------------------------------------------------------
#define GBM 128
#define GBN 128
#define GBK 16
#define SAP 20
#define SBP 136
#define STAGE_A (GBM * SAP)
#define STAGE_B (GBK * SBP)
#define GEMM_NSTAGE 4
#define GEMM_SMEM_BYTES ((GEMM_NSTAGE * (STAGE_A + STAGE_B)) * 4)

__global__ __launch_bounds__(256, 2) void gemm_tf32(
    const unsigned* __restrict__ A, const unsigned* __restrict__ B,
    const float* __restrict__ bias, float* __restrict__ C,
    int M, int N, int K, int mode,
    __half* __restrict__ qh, __half* __restrict__ kh, __half* __restrict__ vt)
{
    extern __shared__ unsigned gsm[];
    unsigned* As = gsm;
    unsigned* Bs = gsm + GEMM_NSTAGE * STAGE_A;
    const uint32_t as_u = (uint32_t)__cvta_generic_to_shared(As);
    const uint32_t bs_u = (uint32_t)__cvta_generic_to_shared(Bs);

    const int tid  = threadIdx.x;
    const int lane = tid & 31;
    const int warp = tid >> 5;
    const int wm   = warp & 3;
    const int wn   = warp >> 2;
    const int r    = lane >> 2;
    const int q    = lane & 3;
    const int bm   = blockIdx.y * GBM;
    const int bn   = blockIdx.x * GBN;

    const int am0 = tid >> 2;
    const int akg = (tid & 3) * 4;
    const int bk0 = tid >> 5;
    const int bn4 = (tid & 31) * 4;

    const unsigned* Ag0 = A + (size_t)(bm + am0) * K + akg;
    const unsigned* Ag1 = A + (size_t)(bm + am0 + 64) * K + akg;
    const unsigned* Bg0 = B + (size_t)bk0 * N + bn + bn4;
    const unsigned* Bg1 = B + (size_t)(bk0 + 8) * N + bn + bn4;

    const int nslab = K / GBK;

    auto stage = [&](int slab) {
        const int buf = slab & 3;
        const uint32_t ad = as_u + (uint32_t)(buf * STAGE_A) * 4;
        const uint32_t bd = bs_u + (uint32_t)(buf * STAGE_B) * 4;
        const int koff = slab * GBK;
        cp16(ad + (uint32_t)(am0 * SAP + akg) * 4,        Ag0 + koff);
        cp16(ad + (uint32_t)((am0 + 64) * SAP + akg) * 4, Ag1 + koff);
        cp16(bd + (uint32_t)(bk0 * SBP + bn4) * 4,        Bg0 + (size_t)koff * N);
        cp16(bd + (uint32_t)((bk0 + 8) * SBP + bn4) * 4,  Bg1 + (size_t)koff * N);
        CP_COMMIT();
    };

    float acc[2][8][4];
    #pragma unroll
    for (int i = 0; i < 2; i++)
        #pragma unroll
        for (int j = 0; j < 8; j++)
            #pragma unroll
            for (int k = 0; k < 4; k++) acc[i][j][k] = 0.0f;

    stage(0); stage(1); stage(2);

    #pragma unroll 1
    for (int i = 0; i < nslab; i++) {
        if (i + 2 < nslab) {
            asm volatile("cp.async.wait_group 2;" ::: "memory");
        } else {
            asm volatile("cp.async.wait_group 0;" ::: "memory");
        }
        __syncthreads();

        if (i + 3 < nslab) stage(i + 3);

        const int buf = i & 3;
        const unsigned* Asb = As + buf * STAGE_A;
        const unsigned* Bsb = Bs + buf * STAGE_B;

        #pragma unroll
        for (int kk = 0; kk < GBK; kk += 8) {
            unsigned af[2][4];
            #pragma unroll
            for (int mt = 0; mt < 2; mt++) {
                const int m = wm * 32 + mt * 16 + r;
                af[mt][0] = Asb[m * SAP + kk + q];
                af[mt][1] = Asb[(m + 8) * SAP + kk + q];
                af[mt][2] = Asb[m * SAP + kk + q + 4];
                af[mt][3] = Asb[(m + 8) * SAP + kk + q + 4];
            }
            #pragma unroll
            for (int nt = 0; nt < 8; nt++) {
                const int n = wn * 64 + nt * 8 + r;
                unsigned bf[2];
                bf[0] = Bsb[(kk + q) * SBP + n];
                bf[1] = Bsb[(kk + q + 4) * SBP + n];
                mma_tf32(acc[0][nt], af[0], bf);
                mma_tf32(acc[1][nt], af[1], bf);
            }
        }
        __syncthreads();
    }

    // epilogue
    #pragma unroll
    for (int mt = 0; mt < 2; mt++) {
        const int row = bm + wm * 32 + mt * 16 + r;
        #pragma unroll
        for (int nt = 0; nt < 8; nt++) {
            const int col = bn + wn * 64 + nt * 8 + 2 * q;
            const float b0 = bias[col], b1 = bias[col + 1];
            float v00 = acc[mt][nt][0] + b0, v01 = acc[mt][nt][1] + b1;
            float v10 = acc[mt][nt][2] + b0, v11 = acc[mt][nt][3] + b1;
            if (mode == 0) {
                *(float2*)(C + (size_t)row * N + col)       = make_float2(v00, v01);
                *(float2*)(C + (size_t)(row + 8) * N + col) = make_float2(v10, v11);
            } else if (col < C_DIM) {
                // Q: scale + fp16
                __half2 h0 = __floats2half2_rn(v00 * 0.125f, v01 * 0.125f);
                __half2 h1 = __floats2half2_rn(v10 * 0.125f, v11 * 0.125f);
                *(__half2*)(qh + (size_t)row * C_DIM + col)       = h0;
                *(__half2*)(qh + (size_t)(row + 8) * C_DIM + col) = h1;
            } else if (col < 2 * C_DIM) {
                __half2 h0 = __floats2half2_rn(v00, v01);
                __half2 h1 = __floats2half2_rn(v10, v11);
                *(__half2*)(kh + (size_t)row * C_DIM + col - C_DIM)       = h0;
                *(__half2*)(kh + (size_t)(row + 8) * C_DIM + col - C_DIM) = h1;
            } else {
                const int d = col - 2 * C_DIM;   // 0..1023 = h*64 + dh
                vt[(size_t)d * T_SEQ + row]           = __float2half_rn(v00);
                vt[(size_t)(d + 1) * T_SEQ + row]     = __float2half_rn(v01);
                vt[(size_t)d * T_SEQ + row + 8]       = __float2half_rn(v10);
                vt[(size_t)(d + 1) * T_SEQ + row + 8] = __float2half_rn(v11);
            }
        }
    }
}

// ---------------------------------------------------------------------------
// Flash attention, fp16 m16n8k16 mma. 4 warps x 16 q rows = 64 q rows/block.
// K smem: [64 kv][72 halfs]; V smem (head-transposed): [64 dh][72 halfs].
// Double-buffered cp.async. P kept in registers (S layout == PV A layout).
// ---------------------------------------------------------------------------
#define AST 72                       // padded row stride (halfs)
#define TILE_H (64 * AST)            // halfs per tile
#define ATTN_SMEM_BYTES (4 * TILE_H * 2)   // 2 tiles x 2 buffers x 2B

__global__ __launch_bounds__(128, 3) void attn_f16(
    const __half* __restrict__ qh, const __half* __restrict__ kh,
    const __half* __restrict__ vt, float* __restrict__ attn_out)
{
    extern __shared__ __half hsm[];
    __half* Ksb = hsm;                    // [2][64][AST]
    __half* Vsb = hsm + 2 * TILE_H;       // [2][64][AST]
    const uint32_t ks_u = (uint32_t)__cvta_generic_to_shared(Ksb);
    const uint32_t vs_u = (uint32_t)__cvta_generic_to_shared(Vsb);

    const int h    = blockIdx.y;
    const int qb   = blockIdx.x;
    const int tid  = threadIdx.x;
    const int lane = tid & 31;
    const int warp = tid >> 5;
    const int r    = lane >> 2;
    const int q    = lane & 3;

    // Q fragments (fp16, pre-scaled): a-frags for 4 k16 steps over dh=64
    unsigned qa[4][4];
    const int qrow = qb * 64 + warp * 16 + r;
    const __half* qp0 = qh + (size_t)qrow * C_DIM + h * 64;
    const __half* qp1 = qp0 + (size_t)8 * C_DIM;
    #pragma unroll
    for (int ks = 0; ks < 4; ks++) {
        qa[ks][0] = *(const unsigned*)(qp0 + 16 * ks + 2 * q);
        qa[ks][1] = *(const unsigned*)(qp1 + 16 * ks + 2 * q);
        qa[ks][2] = *(const unsigned*)(qp0 + 16 * ks + 2 * q + 8);
        qa[ks][3] = *(const unsigned*)(qp1 + 16 * ks + 2 * q + 8);
    }

    float o[8][4];
    #pragma unroll
    for (int nt = 0; nt < 8; nt++)
        #pragma unroll
        for (int i = 0; i < 4; i++) o[nt][i] = 0.0f;
    float m0 = -INFINITY, m1 = -INFINITY, l0 = 0.0f, l1 = 0.0f;

    auto stage = [&](int kb, int buf) {
        const uint32_t kd = ks_u + (uint32_t)buf * TILE_H * 2;
        const uint32_t vd = vs_u + (uint32_t)buf * TILE_H * 2;
        #pragma unroll
        for (int i = 0; i < 4; i++) {
            const int chunk = tid + i * 128;    // 0..511
            const int row = chunk >> 3;         // 0..63 (kv row / dh row)
            const int c   = chunk & 7;          // 16B chunk within 128B row
            cp16(kd + (uint32_t)(row * AST) * 2 + c * 16,
                 kh + (size_t)(kb * 64 + row) * C_DIM + h * 64 + c * 8);
            cp16(vd + (uint32_t)(row * AST) * 2 + c * 16,
                 vt + (size_t)(h * 64 + row) * T_SEQ + kb * 64 + c * 8);
        }
        CP_COMMIT();
    };

    stage(0, 0);

    #pragma unroll 1
    for (int kb = 0; kb < T_SEQ / 64; kb++) {
        const int cur = kb & 1;
        const bool has_next = (kb + 1) < T_SEQ / 64;
        if (has_next) {
            stage(kb + 1, cur ^ 1);
            asm volatile("cp.async.wait_group 1;" ::: "memory");
        } else {
            asm volatile("cp.async.wait_group 0;" ::: "memory");
        }
        __syncthreads();

        const __half* Kst = Ksb + cur * TILE_H;
        const __half* Vst = Vsb + cur * TILE_H;

        // S = Q @ K^T (16x64 per warp), fp32 accum
        float p[8][4];
        #pragma unroll
        for (int nt = 0; nt < 8; nt++)
            #pragma unroll
            for (int i = 0; i < 4; i++) p[nt][i] = 0.0f;

        #pragma unroll
        for (int ks = 0; ks < 4; ks++) {
            #pragma unroll
            for (int nt = 0; nt < 8; nt++) {
                const __half* kp = Kst + (nt * 8 + r) * AST + 16 * ks + 2 * q;
                unsigned bf[2];
                bf[0] = *(const unsigned*)kp;
                bf[1] = *(const unsigned*)(kp + 8);
                mma_f16(p[nt], qa[ks], bf);
            }
        }

        // online softmax
        float mx0 = -INFINITY, mx1 = -INFINITY;
        #pragma unroll
        for (int nt = 0; nt < 8; nt++) {
            mx0 = fmaxf(mx0, fmaxf(p[nt][0], p[nt][1]));
            mx1 = fmaxf(mx1, fmaxf(p[nt][2], p[nt][3]));
        }
        #pragma unroll
        for (int off = 1; off < 4; off <<= 1) {
            mx0 = fmaxf(mx0, __shfl_xor_sync(0xffffffffu, mx0, off));
            mx1 = fmaxf(mx1, __shfl_xor_sync(0xffffffffu, mx1, off));
        }
        const float nm0 = fmaxf(m0, mx0);
        const float nm1 = fmaxf(m1, mx1);
        const float al0 = __expf(m0 - nm0);
        const float al1 = __expf(m1 - nm1);
        m0 = nm0; m1 = nm1;

        float rs0 = 0.0f, rs1 = 0.0f;
        #pragma unroll
        for (int nt = 0; nt < 8; nt++) {
            p[nt][0] = __expf(p[nt][0] - m0);
            p[nt][1] = __expf(p[nt][1] - m0);
            p[nt][2] = __expf(p[nt][2] - m1);
            p[nt][3] = __expf(p[nt][3] - m1);
            rs0 += p[nt][0] + p[nt][1];
            rs1 += p[nt][2] + p[nt][3];
            o[nt][0] *= al0; o[nt][1] *= al0;
            o[nt][2] *= al1; o[nt][3] *= al1;
        }
        #pragma unroll
        for (int off = 1; off < 4; off <<= 1) {
            rs0 += __shfl_xor_sync(0xffffffffu, rs0, off);
            rs1 += __shfl_xor_sync(0xffffffffu, rs1, off);
        }
        l0 = l0 * al0 + rs0;
        l1 = l1 * al1 + rs1;

        // O += P @ V : A-frag built directly from p (k16 pairs = col pairs)
        #pragma unroll
        for (int ks = 0; ks < 4; ks++) {
            unsigned af[4];
            __half2 t0 = __floats2half2_rn(p[2 * ks][0],     p[2 * ks][1]);
            __half2 t1 = __floats2half2_rn(p[2 * ks][2],     p[2 * ks][3]);
            __half2 t2 = __floats2half2_rn(p[2 * ks + 1][0], p[2 * ks + 1][1]);
            __half2 t3 = __floats2half2_rn(p[2 * ks + 1][2], p[2 * ks + 1][3]);
            af[0] = *(unsigned*)&t0;
            af[1] = *(unsigned*)&t1;
            af[2] = *(unsigned*)&t2;
            af[3] = *(unsigned*)&t3;
            #pragma unroll
            for (int nt = 0; nt < 8; nt++) {
                const __half* vp = Vst + (nt * 8 + r) * AST + 16 * ks + 2 * q;
                unsigned bf[2];
                bf[0] = *(const unsigned*)vp;
                bf[1] = *(const unsigned*)(vp + 8);
                mma_f16(o[nt], af, bf);
            }
        }
        __syncthreads();
    }

    // normalize, tf32-round (out-proj consumes tf32 bits), store
    const float il0 = 1.0f / l0;
    const float il1 = 1.0f / l1;
    float* op0 = attn_out + (size_t)qrow * C_DIM + h * 64;
    float* op1 = op0 + (size_t)8 * C_DIM;
    #pragma unroll
    for (int nt = 0; nt < 8; nt++) {
        const int col = nt * 8 + 2 * q;
        *(float2*)(op0 + col) = make_float2(
            __uint_as_float(f2tf32(o[nt][0] * il0)),
            __uint_as_float(f2tf32(o[nt][1] * il0)));
        *(float2*)(op1 + col) = make_float2(
            __uint_as_float(f2tf32(o[nt][2] * il1)),
            __uint_as_float(f2tf32(o[nt][3] * il1)));
    }
}

// ---------------------------------------------------------------------------
extern "C" void kernel_launch(void* const* d_in, const int* in_sizes, int n_in,
                              void* d_out, int out_size)
{
    const float* x    = (const float*)d_in[0];
    const float* Wqkv = (const float*)d_in[1];
    const float* bqkv = (const float*)d_in[2];
    const float* Wout = (const float*)d_in[3];
    const float* bout = (const float*)d_in[4];
    float* out = (float*)d_out;

    float *attn, *xc, *wqkvc, *woutc;
    __half *qh, *kh, *vt;
    cudaGetSymbolAddress((void**)&attn,  g_attn);
    cudaGetSymbolAddress((void**)&xc,    g_xc);
    cudaGetSymbolAddress((void**)&wqkvc, g_wqkvc);
    cudaGetSymbolAddress((void**)&woutc, g_woutc);
    cudaGetSymbolAddress((void**)&qh,    g_qh);
    cudaGetSymbolAddress((void**)&kh,    g_kh);
    cudaGetSymbolAddress((void**)&vt,    g_vt);

    cudaFuncSetAttribute(gemm_tf32, cudaFuncAttributeMaxDynamicSharedMemorySize,
                         GEMM_SMEM_BYTES);
    cudaFuncSetAttribute(attn_f16, cudaFuncAttributeMaxDynamicSharedMemorySize,
                         ATTN_SMEM_BYTES);

    // 0) prepass: fp32 -> tf32 bits
    const int n4x = T_SEQ * C_DIM / 4;
    const int n4w = C_DIM * QKV_N / 4;
    const int n4o = C_DIM * C_DIM / 4;
    cvt_tf32_kernel<<<(n4x + 255) / 256, 256>>>((const float4*)x,    (float4*)xc,    n4x);
    cvt_tf32_kernel<<<(n4w + 255) / 256, 256>>>((const float4*)Wqkv, (float4*)wqkvc, n4w);
    cvt_tf32_kernel<<<(n4o + 255) / 256, 256>>>((const float4*)Wout, (float4*)woutc, n4o);

    // 1) QKV projection -> fp16 Q/K/V (V head-transposed)
    gemm_tf32<<<dim3(QKV_N / GBN, T_SEQ / GBM), 256, GEMM_SMEM_BYTES>>>(
        (const unsigned*)xc, (const unsigned*)wqkvc, bqkv, nullptr,
        T_SEQ, QKV_N, C_DIM, 1, qh, kh, vt);

    // 2) Multi-head flash attention (fp16 tensor cores, fp32 softmax)
    attn_f16<<<dim3(T_SEQ / 64, H_NUM), 128, ATTN_SMEM_BYTES>>>(qh, kh, vt, attn);

    // 3) Output projection (tf32, fp32 out)
    gemm_tf32<<<dim3(C_DIM / GBN, T_SEQ / GBM), 256, GEMM_SMEM_BYTES>>>(
        (const unsigned*)attn, (const unsigned*)woutc, bout, out,
        T_SEQ, C_DIM, C_DIM, 0, nullptr, nullptr, nullptr);
}